// round 1
// baseline (speedup 1.0000x reference)
#include <cuda_runtime.h>
#include <math.h>
#include <stddef.h>

// ---------------------------------------------------------------------------
// AttnDecoderRNN2 single decoder step, algebraically reduced:
//  * attention window is always t in [0,9]  (one-hot a0, lengths >= 1000)
//  * global softmax max cancels in L1 normalization -> only t<10 logits needed
//  * LSTM initial state is zero -> Whh unused, f-gate dead
// ---------------------------------------------------------------------------

#define N_B     64
#define T_ENC   2000
#define ENC     512
#define ATT     256
#define DEC     256
#define SPK     64
#define OUT_O   80
#define H4      1024
#define G4      4096
#define IN_LSTM 832
#define DECCAT  1536   // ENC + H4
#define NWIN    10

#define ATT_SPLITK 4
#define G_SPLITK   4
#define O_SPLITK   16

// scratch (device globals; no allocation allowed)
__device__ float g_Xg[N_B * NWIN * ENC];     // gathered enc rows t<10
__device__ float g_pre[N_B * DEC];
__device__ float g_sp[N_B * ENC];
__device__ float g_sb[N_B * ATT];
__device__ float g_inlstm[N_B * IN_LSTM];
__device__ float g_h1[N_B * H4];
__device__ float g_dec[N_B * DECCAT];        // [h2 (1024), context (512)]
__device__ float g_parts[1 << 20];           // split-K partials (reused)

__device__ __forceinline__ float sigm(float x) { return 1.f / (1.f + expf(-x)); }

// ---------------------------------------------------------------------------
// prep: prenet, speed-proj, spkr attention bias, gather enc rows. 4 n / block.
// ---------------------------------------------------------------------------
__global__ void prep_kernel(const float* __restrict__ input_enc,
                            const float* __restrict__ input_dec,
                            const float* __restrict__ spkr,
                            const float* __restrict__ speed,
                            const float* __restrict__ W_p1, const float* __restrict__ b_p1,
                            const float* __restrict__ W_p2, const float* __restrict__ b_p2,
                            const float* __restrict__ W_sp1, const float* __restrict__ b_sp1,
                            const float* __restrict__ W_sp2, const float* __restrict__ b_sp2,
                            const float* __restrict__ W_spkr)
{
    int n0 = blockIdx.x * 4;
    int tid = threadIdx.x;  // 256

    __shared__ float xin[4][144];
    __shared__ float p1s[4][512];
    __shared__ float s1s[4][256];
    __shared__ float spks[4][64];

    for (int i = tid; i < 4 * 144; i += 256) {
        int nn = i / 144, k = i % 144;
        float v = (k < 80) ? input_dec[(n0 + nn) * OUT_O + k]
                           : spkr[(n0 + nn) * SPK + (k - 80)];
        xin[nn][k] = v;
        if (k >= 80) spks[nn][k - 80] = v;
    }
    __syncthreads();

    // prenet layer 1: 512 outputs (ReLU)
    for (int j = tid; j < 512; j += 256) {
        const float* w = W_p1 + j * 144;
        float b = b_p1[j];
        float acc[4] = {b, b, b, b};
        for (int k = 0; k < 144; k++) {
            float wv = w[k];
            #pragma unroll
            for (int nn = 0; nn < 4; nn++) acc[nn] += wv * xin[nn][k];
        }
        #pragma unroll
        for (int nn = 0; nn < 4; nn++) p1s[nn][j] = fmaxf(acc[nn], 0.f);
    }
    // speed-proj layer 1 (ReLU)
    {
        int j = tid;
        float w1 = W_sp1[j], b1 = b_sp1[j];
        #pragma unroll
        for (int nn = 0; nn < 4; nn++)
            s1s[nn][j] = fmaxf(speed[n0 + nn] * w1 + b1, 0.f);
    }
    __syncthreads();

    // prenet layer 2: pre (ReLU)
    {
        int j = tid;
        const float* w = W_p2 + j * 512;
        float b = b_p2[j];
        float acc[4] = {b, b, b, b};
        for (int k = 0; k < 512; k++) {
            float wv = w[k];
            #pragma unroll
            for (int nn = 0; nn < 4; nn++) acc[nn] += wv * p1s[nn][k];
        }
        #pragma unroll
        for (int nn = 0; nn < 4; nn++) g_pre[(n0 + nn) * DEC + j] = fmaxf(acc[nn], 0.f);
    }
    // speed-proj layer 2: sp (tanh)
    for (int e = tid; e < 512; e += 256) {
        const float* w = W_sp2 + e * 256;
        float b = b_sp2[e];
        float acc[4] = {b, b, b, b};
        for (int k = 0; k < 256; k++) {
            float wv = w[k];
            #pragma unroll
            for (int nn = 0; nn < 4; nn++) acc[nn] += wv * s1s[nn][k];
        }
        #pragma unroll
        for (int nn = 0; nn < 4; nn++) g_sp[(n0 + nn) * ENC + e] = tanhf(acc[nn]);
    }
    // spkr attention bias (softsign)
    {
        int a = tid;
        const float* w = W_spkr + a * SPK;
        float acc[4] = {0, 0, 0, 0};
        for (int k = 0; k < SPK; k++) {
            float wv = w[k];
            #pragma unroll
            for (int nn = 0; nn < 4; nn++) acc[nn] += wv * spks[nn][k];
        }
        #pragma unroll
        for (int nn = 0; nn < 4; nn++) {
            float v = acc[nn];
            g_sb[(n0 + nn) * ATT + a] = v / (1.f + fabsf(v));
        }
    }
    // gather enc rows t<10
    for (int i = tid; i < 4 * NWIN * ENC; i += 256) {
        int nn = i / (NWIN * ENC);
        int rem = i % (NWIN * ENC);
        int t = rem >> 9, e = rem & 511;
        g_Xg[((n0 + nn) * NWIN + t) * ENC + e] =
            input_enc[((size_t)(n0 + nn) * T_ENC + t) * ENC + e];
    }
}

// ---------------------------------------------------------------------------
// Generic split-K GEMM: parts[s][m][J] = X[m][0:K] . W[j][0:K] over k-chunk s.
// Tile 64(m) x 64(j) x 32(k), 256 threads, 4x4 outputs/thread.
// ---------------------------------------------------------------------------
__global__ void gemm_kernel(int xsel, const float* __restrict__ W,
                            int M, int J, int K, int ldx, int chunk)
{
    const float* X = (xsel == 0) ? g_Xg : (xsel == 1) ? g_inlstm
                   : (xsel == 2) ? g_h1 : g_dec;
    int j0 = blockIdx.x * 64;
    int s  = blockIdx.y;
    int m0 = blockIdx.z * 64;
    int kbeg = s * chunk;
    int kend = min(K, kbeg + chunk);

    __shared__ float Xs[32][68];
    __shared__ float Ws[32][68];

    int tid = threadIdx.x;
    int tx = tid & 15, ty = tid >> 4;
    int nn = tx * 4, jj = ty * 4;
    float acc[4][4] = {};

    int lr  = tid >> 2;        // 0..63
    int lc0 = (tid & 3) * 4;   // 0,4,8,12

    for (int k0 = kbeg; k0 < kend; k0 += 32) {
        #pragma unroll
        for (int p = 0; p < 2; p++) {
            int kc = lc0 + p * 16;
            int gk = k0 + kc;
            // X tile (rows always valid: M is a multiple of 64 in all uses)
            float4 xv = make_float4(0.f, 0.f, 0.f, 0.f);
            {
                const float* src = X + (size_t)(m0 + lr) * ldx + gk;
                if (gk + 3 < kend) xv = *(const float4*)src;
                else {
                    if (gk + 0 < kend) xv.x = src[0];
                    if (gk + 1 < kend) xv.y = src[1];
                    if (gk + 2 < kend) xv.z = src[2];
                    if (gk + 3 < kend) xv.w = src[3];
                }
            }
            Xs[kc + 0][lr] = xv.x; Xs[kc + 1][lr] = xv.y;
            Xs[kc + 2][lr] = xv.z; Xs[kc + 3][lr] = xv.w;
            // W tile
            float4 wv = make_float4(0.f, 0.f, 0.f, 0.f);
            {
                int gj = j0 + lr;
                if (gj < J) {
                    const float* src = W + (size_t)gj * K + gk;
                    if (gk + 3 < kend) wv = *(const float4*)src;
                    else {
                        if (gk + 0 < kend) wv.x = src[0];
                        if (gk + 1 < kend) wv.y = src[1];
                        if (gk + 2 < kend) wv.z = src[2];
                        if (gk + 3 < kend) wv.w = src[3];
                    }
                }
            }
            Ws[kc + 0][lr] = wv.x; Ws[kc + 1][lr] = wv.y;
            Ws[kc + 2][lr] = wv.z; Ws[kc + 3][lr] = wv.w;
        }
        __syncthreads();
        #pragma unroll
        for (int kk = 0; kk < 32; kk++) {
            float4 xr = *(const float4*)&Xs[kk][nn];
            float4 wr = *(const float4*)&Ws[kk][jj];
            acc[0][0] += xr.x * wr.x; acc[0][1] += xr.x * wr.y;
            acc[0][2] += xr.x * wr.z; acc[0][3] += xr.x * wr.w;
            acc[1][0] += xr.y * wr.x; acc[1][1] += xr.y * wr.y;
            acc[1][2] += xr.y * wr.z; acc[1][3] += xr.y * wr.w;
            acc[2][0] += xr.z * wr.x; acc[2][1] += xr.z * wr.y;
            acc[2][2] += xr.z * wr.z; acc[2][3] += xr.z * wr.w;
            acc[3][0] += xr.w * wr.x; acc[3][1] += xr.w * wr.y;
            acc[3][2] += xr.w * wr.z; acc[3][3] += xr.w * wr.w;
        }
        __syncthreads();
    }

    #pragma unroll
    for (int i = 0; i < 4; i++) {
        size_t rowo = ((size_t)s * M + (m0 + nn + i)) * J;
        #pragma unroll
        for (int q = 0; q < 4; q++) {
            int gj = j0 + jj + q;
            if (gj < J) g_parts[rowo + gj] = acc[i][q];
        }
    }
}

// ---------------------------------------------------------------------------
// attention epilogue: softsign bias, conv(one-hot) bias, logits, windowed
// softmax, context, in_lstm assembly. One block per n.
// ---------------------------------------------------------------------------
__global__ void att_finish(const float* __restrict__ b_enc,
                           const float* __restrict__ conv_prev,
                           const float* __restrict__ W_speed_att,
                           const float* __restrict__ W_proj,
                           const float* __restrict__ b_proj,
                           const float* __restrict__ speed,
                           const int* __restrict__ lengths,
                           const float* __restrict__ spkr,
                           float* __restrict__ out_ctx, int write_ctx)
{
    int n = blockIdx.x;
    int a = threadIdx.x;  // 256 == ATT
    __shared__ float red[256];
    __shared__ float logit_s[NWIN];
    __shared__ float att_s[NWIN];

    float sb    = g_sb[n * ATT + a];
    float spw   = speed[n] * W_speed_att[a];
    float wproj = W_proj[a];
    float be    = b_enc[a];

    float v[NWIN];
    #pragma unroll
    for (int t = 0; t < NWIN; t++) {
        float dot = be;
        #pragma unroll
        for (int s = 0; s < ATT_SPLITK; s++)
            dot += g_parts[((size_t)s * (N_B * NWIN) + n * NWIN + t) * ATT + a];
        float eb = dot / (1.f + fabsf(dot));                 // softsign
        float e  = eb + sb + conv_prev[a * 31 + (15 - t)] + spw;
        v[t] = tanhf(e) * wproj;
    }
    for (int t = 0; t < NWIN; t++) {
        red[a] = v[t];
        __syncthreads();
        for (int st = 128; st > 0; st >>= 1) {
            if (a < st) red[a] += red[a + st];
            __syncthreads();
        }
        if (a == 0) logit_s[t] = red[0] + b_proj[0];
        __syncthreads();
    }
    if (a == 0) {
        int len1 = max(lengths[n], 1) - 1;
        int hi = min(9, len1);        // lo = 0 (argmax of one-hot a0 is 0)
        float m = -1e30f;
        for (int t = 0; t <= hi; t++) m = fmaxf(m, logit_s[t]);
        float ss = 0.f;
        for (int t = 0; t < NWIN; t++) {
            float w = (t <= hi) ? expf(logit_s[t] - m) : 0.f;
            att_s[t] = w; ss += w;
        }
        float inv = 1.f / fmaxf(ss, 1e-12f);
        for (int t = 0; t < NWIN; t++) att_s[t] *= inv;
    }
    __syncthreads();

    // context = sum_t att_t * enc[t] + sp   (sum att = 1)
    for (int e = a; e < ENC; e += 256) {
        float c = g_sp[n * ENC + e];
        #pragma unroll
        for (int t = 0; t < NWIN; t++)
            c += att_s[t] * g_Xg[(n * NWIN + t) * ENC + e];
        g_inlstm[n * IN_LSTM + DEC + e] = c;
        g_dec[n * DECCAT + H4 + e] = c;
        if (write_ctx) out_ctx[n * ENC + e] = c;
    }
    g_inlstm[n * IN_LSTM + a] = g_pre[n * DEC + a];
    if (a < SPK) g_inlstm[n * IN_LSTM + DEC + ENC + a] = spkr[n * SPK + a];
}

// ---------------------------------------------------------------------------
// LSTM gate activation (zero initial state: f-gate dead, Whh unused)
// ---------------------------------------------------------------------------
__global__ void lstm_act(int layer, const float* __restrict__ bih,
                         const float* __restrict__ bhh)
{
    int idx = blockIdx.x * 256 + threadIdx.x;  // 64*1024
    int n = idx >> 10, u = idx & 1023;
    size_t base = (size_t)n * G4;
    float gi = bih[u] + bhh[u];
    float gg = bih[2048 + u] + bhh[2048 + u];
    float go = bih[3072 + u] + bhh[3072 + u];
    #pragma unroll
    for (int s = 0; s < G_SPLITK; s++) {
        size_t o = (size_t)s * (N_B * G4) + base;
        gi += g_parts[o + u];
        gg += g_parts[o + 2048 + u];
        go += g_parts[o + 3072 + u];
    }
    float c = sigm(gi) * tanhf(gg);
    float h = sigm(go) * tanhf(c);
    if (layer == 0) g_h1[n * H4 + u] = h;
    else            g_dec[n * DECCAT + u] = h;
}

// ---------------------------------------------------------------------------
// output epilogue: sum split-K partials + bias
// ---------------------------------------------------------------------------
__global__ void out_finish(const float* __restrict__ b_out, float* __restrict__ out)
{
    int n = blockIdx.x;
    int j = threadIdx.x;  // 160
    float a = b_out[j];
    #pragma unroll
    for (int s = 0; s < O_SPLITK; s++)
        a += g_parts[(size_t)s * (N_B * 160) + n * 160 + j];
    out[n * 160 + j] = a;
}

// ---------------------------------------------------------------------------
extern "C" void kernel_launch(void* const* d_in, const int* in_sizes, int n_in,
                              void* d_out, int out_size)
{
    const float* input_enc   = (const float*)d_in[0];
    const float* input_dec   = (const float*)d_in[1];
    const float* spkr_vec    = (const float*)d_in[2];
    const int*   lengths_enc = (const int*)  d_in[3];
    const float* speed       = (const float*)d_in[4];
    const float* W_enc       = (const float*)d_in[5];
    const float* b_enc       = (const float*)d_in[6];
    const float* W_spkr      = (const float*)d_in[7];
    const float* conv_prev   = (const float*)d_in[8];
    const float* W_speed_att = (const float*)d_in[9];
    const float* W_proj      = (const float*)d_in[10];
    const float* b_proj      = (const float*)d_in[11];
    const float* W_sp1       = (const float*)d_in[12];
    const float* b_sp1       = (const float*)d_in[13];
    const float* W_sp2       = (const float*)d_in[14];
    const float* b_sp2       = (const float*)d_in[15];
    const float* W_p1        = (const float*)d_in[16];
    const float* b_p1        = (const float*)d_in[17];
    const float* W_p2        = (const float*)d_in[18];
    const float* b_p2        = (const float*)d_in[19];
    const float* Wih0        = (const float*)d_in[20];
    /* Whh0 = d_in[21] unused (h0 = 0) */
    const float* bih0        = (const float*)d_in[22];
    const float* bhh0        = (const float*)d_in[23];
    const float* Wih1        = (const float*)d_in[24];
    /* Whh1 = d_in[25] unused */
    const float* bih1        = (const float*)d_in[26];
    const float* bhh1        = (const float*)d_in[27];
    const float* W_out       = (const float*)d_in[28];
    const float* b_out       = (const float*)d_in[29];

    float* out = (float*)d_out;
    int write_ctx = (out_size >= N_B * 2 * OUT_O + N_B * ENC) ? 1 : 0;
    float* ctx_out = out + N_B * 2 * OUT_O;

    // 1. small nets + gather
    prep_kernel<<<16, 256>>>(input_enc, input_dec, spkr_vec, speed,
                             W_p1, b_p1, W_p2, b_p2,
                             W_sp1, b_sp1, W_sp2, b_sp2, W_spkr);
    // 2. attention encoder-bias GEMM: Xg[640,512] . W_enc[256,512]^T
    gemm_kernel<<<dim3(4, ATT_SPLITK, 10), 256>>>(0, W_enc, N_B * NWIN, ATT, ENC, ENC, 128);
    // 3. attention epilogue + context + in_lstm assembly
    att_finish<<<64, 256>>>(b_enc, conv_prev, W_speed_att, W_proj, b_proj,
                            speed, lengths_enc, spkr_vec, ctx_out, write_ctx);
    // 4. LSTM layer 0 input GEMM: in_lstm[64,832] . Wih0[4096,832]^T
    gemm_kernel<<<dim3(64, G_SPLITK, 1), 256>>>(1, Wih0, N_B, G4, IN_LSTM, IN_LSTM, 208);
    lstm_act<<<256, 256>>>(0, bih0, bhh0);
    // 5. LSTM layer 1 GEMM: h1[64,1024] . Wih1[4096,1024]^T
    gemm_kernel<<<dim3(64, G_SPLITK, 1), 256>>>(2, Wih1, N_B, G4, H4, H4, 256);
    lstm_act<<<256, 256>>>(1, bih1, bhh1);
    // 6. output GEMM: dec[64,1536] . W_out[160,1536]^T
    gemm_kernel<<<dim3(3, O_SPLITK, 1), 256>>>(3, W_out, N_B, 160, DECCAT, DECCAT, 96);
    out_finish<<<64, 160>>>(b_out, out);
}

// round 2
// speedup vs baseline: 1.5793x; 1.5793x over previous
#include <cuda_runtime.h>
#include <math.h>
#include <stddef.h>

// ---------------------------------------------------------------------------
// AttnDecoderRNN2 single step, algebraically reduced (validated round 1):
//  * attention window always t in [0,9]; softmax max cancels in L1 norm
//  * zero LSTM state -> Whh unused, f-gate dead
// Round 2: unified f32x2-packed GEMM kernel, fused loaders/epilogues,
// wave-balanced grids (288 blocks for LSTM GEMMs), 8 launches total.
// ---------------------------------------------------------------------------

#define N_B     64
#define T_ENC   2000
#define ENC     512
#define ATT     256
#define H4      1024
#define G4      4096
#define IN_LSTM 832
#define DECCAT  1536
#define NWIN    10
#define OUT_J   160

#define S_ATT 4
#define S_L   9        // split-K for LSTM gemms (l1 s=8 is a zero block)
#define S_OUT 8

typedef unsigned long long u64;

// scratch
__device__ __align__(16) float g_parts [S_L * N_B * G4];     // 2.36M floats, reused
__device__ __align__(16) float g_parts2[2 * N_B * ATT];      // prenet2 partials
__device__ __align__(16) float g_p1    [N_B * 512];
__device__ __align__(16) float g_sp    [N_B * ENC];
__device__ __align__(16) float g_sb    [N_B * ATT];
__device__ __align__(16) float g_inlstm[N_B * IN_LSTM];      // cols 256..831 used
__device__ __align__(16) float g_h1    [N_B * H4];
__device__ __align__(16) float g_dec   [N_B * DECCAT];       // [h2 | context]

struct Ptrs {
    const float *input_enc, *input_dec, *spkr, *speed;
    const float *W_enc, *b_enc, *W_spkr, *conv_prev, *W_speed_att, *W_proj, *b_proj;
    const float *W_sp1, *b_sp1, *W_sp2, *b_sp2;
    const float *W_p1, *b_p1, *W_p2, *b_p2;
    const float *Wih0, *bih0, *bhh0, *Wih1, *bih1, *bhh1, *W_out, *b_out;
    const int *lengths;
    float *out, *ctx_out;
    int write_ctx;
};

__device__ __forceinline__ float sigm(float x) { return 1.f / (1.f + expf(-x)); }

#define FMA2(d, a, b) asm("fma.rn.f32x2 %0,%1,%2,%0;" : "+l"(d) : "l"(a), "l"(b))
#define DUP2(d, s)    asm("mov.b64 %0,{%1,%1};" : "=l"(d) : "f"(s))
#define UNPK(lo, hi, v) asm("mov.b64 {%0,%1},%2;" : "=f"(lo), "=f"(hi) : "l"(v))

enum { M_ATT = 0, M_P1, M_SP2, M_SB, M_P2, M_L0, M_L1, M_OUT };

// ---------------------------------------------------------------------------
// attention epilogue (device func, runs as blocks 0..63 of stage 2)
// ---------------------------------------------------------------------------
__device__ void att_finish_dev(const Ptrs& P)
{
    __shared__ float red[80];
    __shared__ float logit_s[NWIN];
    __shared__ float att_s[NWIN];

    int n = blockIdx.x;
    int a = threadIdx.x;          // 256
    int warp = a >> 5, lane = a & 31;

    float sb    = g_sb[n * ATT + a];
    float spw   = P.speed[n] * P.W_speed_att[a];
    float wproj = P.W_proj[a];
    float be    = P.b_enc[a];

    float v[NWIN];
    #pragma unroll
    for (int t = 0; t < NWIN; t++) {
        float dot = be;
        #pragma unroll
        for (int s = 0; s < S_ATT; s++)
            dot += g_parts[((size_t)s * (N_B * NWIN) + n * NWIN + t) * ATT + a];
        float eb = dot / (1.f + fabsf(dot));
        float e  = eb + sb + P.conv_prev[a * 31 + (15 - t)] + spw;
        v[t] = tanhf(e) * wproj;
    }
    #pragma unroll
    for (int t = 0; t < NWIN; t++) {
        #pragma unroll
        for (int o = 16; o > 0; o >>= 1)
            v[t] += __shfl_xor_sync(0xffffffffu, v[t], o);
    }
    if (lane == 0) {
        #pragma unroll
        for (int t = 0; t < NWIN; t++) red[warp * NWIN + t] = v[t];
    }
    __syncthreads();
    if (a < NWIN) {
        float s = 0.f;
        #pragma unroll
        for (int w = 0; w < 8; w++) s += red[w * NWIN + a];
        logit_s[a] = s + P.b_proj[0];
    }
    __syncthreads();
    if (a == 0) {
        int len1 = max(P.lengths[n], 1) - 1;
        int hi = min(9, len1);
        float m = -1e30f;
        for (int t = 0; t <= hi; t++) m = fmaxf(m, logit_s[t]);
        float ss = 0.f;
        for (int t = 0; t < NWIN; t++) {
            float w = (t <= hi) ? expf(logit_s[t] - m) : 0.f;
            att_s[t] = w; ss += w;
        }
        float inv = 1.f / fmaxf(ss, 1e-12f);
        for (int t = 0; t < NWIN; t++) att_s[t] *= inv;
    }
    __syncthreads();

    for (int e = a; e < ENC; e += 256) {
        float c = g_sp[n * ENC + e];
        #pragma unroll
        for (int t = 0; t < NWIN; t++)
            c += att_s[t] * P.input_enc[((size_t)n * T_ENC + t) * ENC + e];
        g_inlstm[n * IN_LSTM + 256 + e] = c;
        g_dec[(size_t)n * DECCAT + H4 + e] = c;
        if (P.write_ctx) P.ctx_out[n * ENC + e] = c;
    }
    if (a < 64) g_inlstm[n * IN_LSTM + 768 + a] = P.spkr[n * 64 + a];
}

// ---------------------------------------------------------------------------
// unified GEMM + att_finish stage kernel. Tile 64m x 128j x 16k, 256 threads.
// f32x2 packed inner loop: each thread 8m x 4j = 32 MACs / 16 FFMA2 per kk.
// ---------------------------------------------------------------------------
__global__ void __launch_bounds__(256, 2) stage_k(int stage, Ptrs P)
{
    __shared__ __align__(16) float Xs[16][72];
    __shared__ __align__(16) float Ws[16][132];

    int tid = threadIdx.x;

    // ---- block decode ----
    int mode, jt = 0, s = 0, mt = 0;
    if (stage == 1) {
        int b = blockIdx.x;
        if (b < 80)      { mode = M_ATT; jt = b & 1; s = (b >> 1) & 3; mt = b >> 3; }
        else if (b < 84) { mode = M_P1;  jt = b - 80; }
        else if (b < 88) { mode = M_SP2; jt = b - 84; }
        else             { mode = M_SB;  jt = b - 88; }
    } else if (stage == 2) {
        if (blockIdx.x < 64) { att_finish_dev(P); return; }
        int b = blockIdx.x - 64;
        mode = M_P2; jt = b & 1; s = b >> 1;
    } else if (stage == 3) { mode = M_L0;  jt = blockIdx.x & 31; s = blockIdx.x >> 5; }
    else if (stage == 4)   { mode = M_L1;  jt = blockIdx.x & 31; s = blockIdx.x >> 5; }
    else                   { mode = M_OUT; jt = blockIdx.x & 1;  s = blockIdx.x >> 1; }

    int K, chunk, J;
    const float* W;
    switch (mode) {
        case M_ATT: K = 512;  chunk = 128; J = 256;   W = P.W_enc;  break;
        case M_P1:  K = 144;  chunk = 144; J = 512;   W = P.W_p1;   break;
        case M_SP2: K = 256;  chunk = 256; J = 512;   W = P.W_sp2;  break;
        case M_SB:  K = 64;   chunk = 64;  J = 256;   W = P.W_spkr; break;
        case M_P2:  K = 512;  chunk = 256; J = 256;   W = P.W_p2;   break;
        case M_L0:  K = 832;  chunk = 96;  J = G4;    W = P.Wih0;   break;
        case M_L1:  K = 1024; chunk = 128; J = G4;    W = P.Wih1;   break;
        default:    K = 1536; chunk = 192; J = OUT_J; W = P.W_out;  break;
    }
    int j0 = jt * 128, m0 = mt * 64;
    int kbeg = s * chunk;
    int kend = min(K, kbeg + chunk);

    // ---- loader setup: thread loads row (tid>>2), 4 k's at (tid&3)*4 ----
    int mrow = tid >> 2;          // 0..63
    int kc   = (tid & 3) * 4;
    int mg   = m0 + mrow;
    const float* xrow = 0; const float *p2a = 0, *p2b = 0; float spd = 0.f;
    switch (mode) {
        case M_ATT: { int n = mg / 10; int t = mg - n * 10;
                      xrow = P.input_enc + ((size_t)n * T_ENC + t) * ENC; } break;
        case M_P1:  xrow = P.input_dec + mg * 80; break;
        case M_SP2: spd = P.speed[mg]; break;
        case M_SB:  xrow = P.spkr + mg * 64; break;
        case M_P2:  xrow = g_p1 + mg * 512; break;
        case M_L0:  xrow = g_inlstm + mg * IN_LSTM;
                    p2a = g_parts2 + mg * ATT; p2b = g_parts2 + (N_B + mg) * ATT; break;
        case M_L1:  xrow = g_h1 + (size_t)mg * H4; break;
        default:    xrow = g_dec + (size_t)mg * DECCAT; break;
    }

    int warp = tid >> 5, lane = tid & 31;
    int mw = warp * 8;
    int j4 = lane * 4;
    u64 acc[4][4] = {};

    for (int k0 = kbeg; k0 < kend; k0 += 16) {
        int kg = k0 + kc;
        float4 xv;
        if (mode == M_SP2) {
            xv.x = fmaxf(spd * P.W_sp1[kg]     + P.b_sp1[kg],     0.f);
            xv.y = fmaxf(spd * P.W_sp1[kg + 1] + P.b_sp1[kg + 1], 0.f);
            xv.z = fmaxf(spd * P.W_sp1[kg + 2] + P.b_sp1[kg + 2], 0.f);
            xv.w = fmaxf(spd * P.W_sp1[kg + 3] + P.b_sp1[kg + 3], 0.f);
        } else if (mode == M_P1) {
            xv = (kg < 80) ? *(const float4*)(xrow + kg)
                           : *(const float4*)(P.spkr + mg * 64 + (kg - 80));
        } else if (mode == M_L0 && kg < 256) {
            float4 bb = *(const float4*)(P.b_p2 + kg);
            float4 pa = *(const float4*)(p2a + kg);
            float4 pb = *(const float4*)(p2b + kg);
            xv.x = fmaxf(bb.x + pa.x + pb.x, 0.f);
            xv.y = fmaxf(bb.y + pa.y + pb.y, 0.f);
            xv.z = fmaxf(bb.z + pa.z + pb.z, 0.f);
            xv.w = fmaxf(bb.w + pa.w + pb.w, 0.f);
        } else {
            xv = *(const float4*)(xrow + kg);
        }
        Xs[kc + 0][mrow] = xv.x; Xs[kc + 1][mrow] = xv.y;
        Xs[kc + 2][mrow] = xv.z; Xs[kc + 3][mrow] = xv.w;

        #pragma unroll
        for (int r = 0; r < 2; r++) {
            int jrow = r * 64 + mrow;
            int gj = j0 + jrow;
            float4 wv = make_float4(0.f, 0.f, 0.f, 0.f);
            if (gj < J) wv = *(const float4*)(W + (size_t)gj * K + kg);
            Ws[kc + 0][jrow] = wv.x; Ws[kc + 1][jrow] = wv.y;
            Ws[kc + 2][jrow] = wv.z; Ws[kc + 3][jrow] = wv.w;
        }
        __syncthreads();

        #pragma unroll
        for (int kk = 0; kk < 16; kk++) {
            ulonglong2 a01 = *(const ulonglong2*)&Xs[kk][mw];
            ulonglong2 a23 = *(const ulonglong2*)&Xs[kk][mw + 4];
            float4 w = *(const float4*)&Ws[kk][j4];
            u64 w0, w1, w2, w3;
            DUP2(w0, w.x); DUP2(w1, w.y); DUP2(w2, w.z); DUP2(w3, w.w);
            FMA2(acc[0][0], a01.x, w0); FMA2(acc[0][1], a01.x, w1);
            FMA2(acc[0][2], a01.x, w2); FMA2(acc[0][3], a01.x, w3);
            FMA2(acc[1][0], a01.y, w0); FMA2(acc[1][1], a01.y, w1);
            FMA2(acc[1][2], a01.y, w2); FMA2(acc[1][3], a01.y, w3);
            FMA2(acc[2][0], a23.x, w0); FMA2(acc[2][1], a23.x, w1);
            FMA2(acc[2][2], a23.x, w2); FMA2(acc[2][3], a23.x, w3);
            FMA2(acc[3][0], a23.y, w0); FMA2(acc[3][1], a23.y, w1);
            FMA2(acc[3][2], a23.y, w2); FMA2(acc[3][3], a23.y, w3);
        }
        __syncthreads();
    }

    // ---- epilogue ----
    int Mtot = (mode == M_ATT) ? (N_B * NWIN) : N_B;
    #pragma unroll
    for (int p = 0; p < 4; p++) {
        int r0 = mw + 2 * p;
        #pragma unroll
        for (int q = 0; q < 4; q++) {
            float vlo, vhi;
            UNPK(vlo, vhi, acc[p][q]);
            int jg = j0 + j4 + q;
            switch (mode) {
                case M_P1: {
                    float b = P.b_p1[jg];
                    g_p1[(m0 + r0) * 512 + jg]     = fmaxf(vlo + b, 0.f);
                    g_p1[(m0 + r0 + 1) * 512 + jg] = fmaxf(vhi + b, 0.f);
                } break;
                case M_SP2: {
                    float b = P.b_sp2[jg];
                    g_sp[(m0 + r0) * ENC + jg]     = tanhf(vlo + b);
                    g_sp[(m0 + r0 + 1) * ENC + jg] = tanhf(vhi + b);
                } break;
                case M_SB: {
                    g_sb[(m0 + r0) * ATT + jg]     = vlo / (1.f + fabsf(vlo));
                    g_sb[(m0 + r0 + 1) * ATT + jg] = vhi / (1.f + fabsf(vhi));
                } break;
                case M_P2: {
                    size_t base = ((size_t)s * N_B + (m0 + r0)) * ATT + jg;
                    g_parts2[base] = vlo; g_parts2[base + ATT] = vhi;
                } break;
                default: {
                    if (jg < J) {
                        size_t base = ((size_t)s * Mtot + (m0 + r0)) * J + jg;
                        g_parts[base] = vlo; g_parts[base + J] = vhi;
                    }
                } break;
            }
        }
    }
}

// ---------------------------------------------------------------------------
__global__ void lstm_act(int layer, const float* __restrict__ bih,
                         const float* __restrict__ bhh)
{
    int idx = blockIdx.x * 256 + threadIdx.x;   // 64*1024
    int n = idx >> 10, u = idx & 1023;
    float gi = bih[u] + bhh[u];
    float gg = bih[2048 + u] + bhh[2048 + u];
    float go = bih[3072 + u] + bhh[3072 + u];
    #pragma unroll
    for (int s = 0; s < S_L; s++) {
        size_t base = ((size_t)s * N_B + n) * G4;
        gi += g_parts[base + u];
        gg += g_parts[base + 2048 + u];
        go += g_parts[base + 3072 + u];
    }
    float c = sigm(gi) * tanhf(gg);
    float h = sigm(go) * tanhf(c);
    if (layer == 0) g_h1[n * H4 + u] = h;
    else            g_dec[(size_t)n * DECCAT + u] = h;
}

__global__ void out_finish(const float* __restrict__ b_out, float* __restrict__ out)
{
    int n = blockIdx.x;
    int j = threadIdx.x;    // 160
    float a = b_out[j];
    #pragma unroll
    for (int s = 0; s < S_OUT; s++)
        a += g_parts[((size_t)s * N_B + n) * OUT_J + j];
    out[n * OUT_J + j] = a;
}

// ---------------------------------------------------------------------------
extern "C" void kernel_launch(void* const* d_in, const int* in_sizes, int n_in,
                              void* d_out, int out_size)
{
    Ptrs P;
    P.input_enc   = (const float*)d_in[0];
    P.input_dec   = (const float*)d_in[1];
    P.spkr        = (const float*)d_in[2];
    P.lengths     = (const int*)  d_in[3];
    P.speed       = (const float*)d_in[4];
    P.W_enc       = (const float*)d_in[5];
    P.b_enc       = (const float*)d_in[6];
    P.W_spkr      = (const float*)d_in[7];
    P.conv_prev   = (const float*)d_in[8];
    P.W_speed_att = (const float*)d_in[9];
    P.W_proj      = (const float*)d_in[10];
    P.b_proj      = (const float*)d_in[11];
    P.W_sp1       = (const float*)d_in[12];
    P.b_sp1       = (const float*)d_in[13];
    P.W_sp2       = (const float*)d_in[14];
    P.b_sp2       = (const float*)d_in[15];
    P.W_p1        = (const float*)d_in[16];
    P.b_p1        = (const float*)d_in[17];
    P.W_p2        = (const float*)d_in[18];
    P.b_p2        = (const float*)d_in[19];
    P.Wih0        = (const float*)d_in[20];
    P.bih0        = (const float*)d_in[22];
    P.bhh0        = (const float*)d_in[23];
    P.Wih1        = (const float*)d_in[24];
    P.bih1        = (const float*)d_in[26];
    P.bhh1        = (const float*)d_in[27];
    P.W_out       = (const float*)d_in[28];
    P.b_out       = (const float*)d_in[29];

    float* out = (float*)d_out;
    P.out = out;
    P.write_ctx = (out_size >= N_B * 2 * 80 + N_B * ENC) ? 1 : 0;
    P.ctx_out = out + N_B * 2 * 80;

    // L1: att-bias GEMM (80) + prenet1 (4) + speed-proj2 (4) + spkr-bias (2)
    stage_k<<<90, 256>>>(1, P);
    // L2: att epilogue/context/in_lstm (64) + prenet2 partial GEMM (4)
    stage_k<<<68, 256>>>(2, P);
    // L3: LSTM0 GEMM (fused prenet2 activation in X-loader), 288 blocks
    stage_k<<<288, 256>>>(3, P);
    lstm_act<<<256, 256>>>(0, P.bih0, P.bhh0);
    // L5: LSTM1 GEMM
    stage_k<<<288, 256>>>(4, P);
    lstm_act<<<256, 256>>>(1, P.bih1, P.bhh1);
    // L7: output GEMM
    stage_k<<<16, 256>>>(5, P);
    out_finish<<<64, 160>>>(P.b_out, out);
}

// round 4
// speedup vs baseline: 2.8681x; 1.8161x over previous
#include <cuda_runtime.h>
#include <math.h>
#include <stddef.h>

// ---------------------------------------------------------------------------
// AttnDecoderRNN2 single step, algebraically reduced (validated):
//  * attention window always t in [0,9]; softmax max cancels in L1 norm
//  * zero LSTM state -> Whh unused, f-gate dead (i,g,o rows only: J=3072)
// Round 4: round-3 design with the lstm_act grid bug fixed (192 -> 64 blocks;
// the oversize grid wrote g_h1/g_dec out of bounds -> illegal access).
// ---------------------------------------------------------------------------

#define N_B     64
#define T_ENC   2000
#define ENC     512
#define ATT     256
#define H4      1024
#define G3      3072          // i,g,o gates only
#define IN_LSTM 832
#define DECCAT  1536
#define NWIN    10
#define OUT_J   160

#define S_ATT 4
#define S_L   6
#define S_OUT 8

typedef unsigned long long u64;

// scratch
__device__ __align__(16) float g_parts [S_L * N_B * G3];     // 1.18M floats, reused
__device__ __align__(16) float g_parts2[2 * N_B * ATT];
__device__ __align__(16) float g_p1    [N_B * 512];
__device__ __align__(16) float g_sp    [N_B * ENC];
__device__ __align__(16) float g_sb    [N_B * ATT];
__device__ __align__(16) float g_inlstm[N_B * IN_LSTM];
__device__ __align__(16) float g_h1    [N_B * H4];
__device__ __align__(16) float g_dec   [N_B * DECCAT];       // [h2 | context]

struct Ptrs {
    const float *input_enc, *input_dec, *spkr, *speed;
    const float *W_enc, *b_enc, *W_spkr, *conv_prev, *W_speed_att, *W_proj, *b_proj;
    const float *W_sp1, *b_sp1, *W_sp2, *b_sp2;
    const float *W_p1, *b_p1, *W_p2, *b_p2;
    const float *Wih0, *bih0, *bhh0, *Wih1, *bih1, *bhh1, *W_out, *b_out;
    const int *lengths;
    float *out, *ctx_out;
    int write_ctx;
};

__device__ __forceinline__ float sigm(float x) { return 1.f / (1.f + expf(-x)); }

#define FMA2(d, a, b) asm("fma.rn.f32x2 %0,%1,%2,%0;" : "+l"(d) : "l"(a), "l"(b))
#define DUP2(d, s)    asm("mov.b64 %0,{%1,%1};" : "=l"(d) : "f"(s))
#define UNPK(lo, hi, v) asm("mov.b64 {%0,%1},%2;" : "=f"(lo), "=f"(hi) : "l"(v))

enum { M_ATT = 0, M_P1, M_SP2, M_SB, M_P2, M_L0, M_L1, M_OUT };

// ---------------------------------------------------------------------------
__device__ void att_finish_dev(const Ptrs& P)
{
    __shared__ float red[80];
    __shared__ float logit_s[NWIN];
    __shared__ float att_s[NWIN];

    int n = blockIdx.x;
    int a = threadIdx.x;          // 256
    int warp = a >> 5, lane = a & 31;

    float sb    = g_sb[n * ATT + a];
    float spw   = P.speed[n] * P.W_speed_att[a];
    float wproj = P.W_proj[a];
    float be    = P.b_enc[a];

    float v[NWIN];
    #pragma unroll
    for (int t = 0; t < NWIN; t++) {
        float dot = be;
        #pragma unroll
        for (int s = 0; s < S_ATT; s++)
            dot += g_parts[((size_t)s * (N_B * NWIN) + n * NWIN + t) * ATT + a];
        float eb = dot / (1.f + fabsf(dot));
        float e  = eb + sb + P.conv_prev[a * 31 + (15 - t)] + spw;
        v[t] = tanhf(e) * wproj;
    }
    #pragma unroll
    for (int t = 0; t < NWIN; t++) {
        #pragma unroll
        for (int o = 16; o > 0; o >>= 1)
            v[t] += __shfl_xor_sync(0xffffffffu, v[t], o);
    }
    if (lane == 0) {
        #pragma unroll
        for (int t = 0; t < NWIN; t++) red[warp * NWIN + t] = v[t];
    }
    __syncthreads();
    if (a < NWIN) {
        float s = 0.f;
        #pragma unroll
        for (int w = 0; w < 8; w++) s += red[w * NWIN + a];
        logit_s[a] = s + P.b_proj[0];
    }
    __syncthreads();
    if (a == 0) {
        int len1 = max(P.lengths[n], 1) - 1;
        int hi = min(9, len1);
        float m = -1e30f;
        for (int t = 0; t <= hi; t++) m = fmaxf(m, logit_s[t]);
        float ss = 0.f;
        for (int t = 0; t < NWIN; t++) {
            float w = (t <= hi) ? expf(logit_s[t] - m) : 0.f;
            att_s[t] = w; ss += w;
        }
        float inv = 1.f / fmaxf(ss, 1e-12f);
        for (int t = 0; t < NWIN; t++) att_s[t] *= inv;
    }
    __syncthreads();

    for (int e = a; e < ENC; e += 256) {
        float c = g_sp[n * ENC + e];
        #pragma unroll
        for (int t = 0; t < NWIN; t++)
            c += att_s[t] * P.input_enc[((size_t)n * T_ENC + t) * ENC + e];
        g_inlstm[n * IN_LSTM + 256 + e] = c;
        g_dec[(size_t)n * DECCAT + H4 + e] = c;
        if (P.write_ctx) P.ctx_out[n * ENC + e] = c;
    }
    if (a < 64) g_inlstm[n * IN_LSTM + 768 + a] = P.spkr[n * 64 + a];
}

// ---------------------------------------------------------------------------
// unified double-buffered GEMM. Tile 64m x 128j x 16k, 256 threads.
// ---------------------------------------------------------------------------
__global__ void __launch_bounds__(256, 2) stage_k(int stage, Ptrs P)
{
    __shared__ __align__(16) float Xs[2][16][68];
    __shared__ __align__(16) float Ws[2][16][132];

    int tid = threadIdx.x;

    // ---- block decode ----
    int mode, jt = 0, s = 0, mt = 0;
    if (stage == 1) {
        int b = blockIdx.x;
        if (b < 80)      { mode = M_ATT; jt = b & 1; s = (b >> 1) & 3; mt = b >> 3; }
        else if (b < 84) { mode = M_P1;  jt = b - 80; }
        else if (b < 88) { mode = M_SP2; jt = b - 84; }
        else             { mode = M_SB;  jt = b - 88; }
    } else if (stage == 2) {
        if (blockIdx.x < 64) { att_finish_dev(P); return; }
        int b = blockIdx.x - 64;
        mode = M_P2; jt = b & 1; s = b >> 1;
    } else if (stage == 3) { mode = M_L0;  jt = blockIdx.x % 24; s = blockIdx.x / 24; }
    else if (stage == 4)   { mode = M_L1;  jt = blockIdx.x % 24; s = blockIdx.x / 24; }
    else                   { mode = M_OUT; jt = blockIdx.x & 1;  s = blockIdx.x >> 1; }

    int K, chunk, J;
    const float* W;
    switch (mode) {
        case M_ATT: K = 512;  chunk = 128; J = 256;   W = P.W_enc;  break;
        case M_P1:  K = 144;  chunk = 144; J = 512;   W = P.W_p1;   break;
        case M_SP2: K = 256;  chunk = 256; J = 512;   W = P.W_sp2;  break;
        case M_SB:  K = 64;   chunk = 64;  J = 256;   W = P.W_spkr; break;
        case M_P2:  K = 512;  chunk = 256; J = 256;   W = P.W_p2;   break;
        case M_L0:  K = 832;  chunk = 144; J = G3;    W = P.Wih0;   break;
        case M_L1:  K = 1024; chunk = 176; J = G3;    W = P.Wih1;   break;
        default:    K = 1536; chunk = 192; J = OUT_J; W = P.W_out;  break;
    }
    int lstm = (mode == M_L0 || mode == M_L1);
    int j0 = jt * 128, m0 = mt * 64;
    int kbeg = s * chunk;
    int kend = min(K, kbeg + chunk);
    int nsl  = (kend - kbeg) >> 4;     // all sizes multiples of 16

    // ---- loader setup: thread loads row (tid>>2), 4 k's at (tid&3)*4 ----
    int mrow = tid >> 2;
    int kc   = (tid & 3) * 4;
    int mg   = m0 + mrow;
    const float* xrow = 0; const float *p2a = 0, *p2b = 0; float spd = 0.f;
    switch (mode) {
        case M_ATT: { int n = mg / 10; int t = mg - n * 10;
                      xrow = P.input_enc + ((size_t)n * T_ENC + t) * ENC; } break;
        case M_P1:  xrow = P.input_dec + mg * 80; break;
        case M_SP2: spd = P.speed[mg]; break;
        case M_SB:  xrow = P.spkr + mg * 64; break;
        case M_P2:  xrow = g_p1 + mg * 512; break;
        case M_L0:  xrow = g_inlstm + mg * IN_LSTM;
                    p2a = g_parts2 + mg * ATT; p2b = g_parts2 + (N_B + mg) * ATT; break;
        case M_L1:  xrow = g_h1 + (size_t)mg * H4; break;
        default:    xrow = g_dec + (size_t)mg * DECCAT; break;
    }
    // W row pointers (logical row -> physical, skipping dead f-gate rows:
    // logical [0,1024)=i -> phys same; [1024,2048)=g -> +1024; [2048,3072)=o -> +1024)
    int gj0 = j0 + mrow, gj1 = j0 + 64 + mrow;
    int jp0 = lstm ? (gj0 + (gj0 >= 1024 ? 1024 : 0)) : gj0;
    int jp1 = lstm ? (gj1 + (gj1 >= 1024 ? 1024 : 0)) : gj1;
    const float* wp0 = W + (size_t)jp0 * K;
    const float* wp1 = W + (size_t)jp1 * K;
    bool v0 = gj0 < J, v1 = gj1 < J;

    int warp = tid >> 5, lane = tid & 31;
    int mw = warp * 8;
    int j4 = lane * 4;
    u64 acc[4][4] = {};

    auto load_x = [&](int kg) -> float4 {
        float4 xv;
        if (mode == M_SP2) {
            float4 w1 = *(const float4*)(P.W_sp1 + kg);
            float4 b1 = *(const float4*)(P.b_sp1 + kg);
            xv.x = fmaxf(spd * w1.x + b1.x, 0.f);
            xv.y = fmaxf(spd * w1.y + b1.y, 0.f);
            xv.z = fmaxf(spd * w1.z + b1.z, 0.f);
            xv.w = fmaxf(spd * w1.w + b1.w, 0.f);
        } else if (mode == M_P1) {
            xv = (kg < 80) ? *(const float4*)(xrow + kg)
                           : *(const float4*)(P.spkr + mg * 64 + (kg - 80));
        } else if (mode == M_L0 && kg < 256) {
            float4 bb = *(const float4*)(P.b_p2 + kg);
            float4 pa = *(const float4*)(p2a + kg);
            float4 pb = *(const float4*)(p2b + kg);
            xv.x = fmaxf(bb.x + pa.x + pb.x, 0.f);
            xv.y = fmaxf(bb.y + pa.y + pb.y, 0.f);
            xv.z = fmaxf(bb.z + pa.z + pb.z, 0.f);
            xv.w = fmaxf(bb.w + pa.w + pb.w, 0.f);
        } else {
            xv = *(const float4*)(xrow + kg);
        }
        return xv;
    };

    float4 xv = load_x(kbeg + kc);
    float4 wv0 = v0 ? *(const float4*)(wp0 + kbeg + kc) : make_float4(0, 0, 0, 0);
    float4 wv1 = v1 ? *(const float4*)(wp1 + kbeg + kc) : make_float4(0, 0, 0, 0);

    int buf = 0;
    for (int i = 0; i < nsl; i++) {
        Xs[buf][kc + 0][mrow] = xv.x; Xs[buf][kc + 1][mrow] = xv.y;
        Xs[buf][kc + 2][mrow] = xv.z; Xs[buf][kc + 3][mrow] = xv.w;
        Ws[buf][kc + 0][mrow] = wv0.x; Ws[buf][kc + 1][mrow] = wv0.y;
        Ws[buf][kc + 2][mrow] = wv0.z; Ws[buf][kc + 3][mrow] = wv0.w;
        Ws[buf][kc + 0][64 + mrow] = wv1.x; Ws[buf][kc + 1][64 + mrow] = wv1.y;
        Ws[buf][kc + 2][64 + mrow] = wv1.z; Ws[buf][kc + 3][64 + mrow] = wv1.w;
        __syncthreads();

        if (i + 1 < nsl) {   // prefetch next slice while computing this one
            int kg = kbeg + (i + 1) * 16 + kc;
            xv  = load_x(kg);
            wv0 = v0 ? *(const float4*)(wp0 + kg) : make_float4(0, 0, 0, 0);
            wv1 = v1 ? *(const float4*)(wp1 + kg) : make_float4(0, 0, 0, 0);
        }

        #pragma unroll
        for (int kk = 0; kk < 16; kk++) {
            ulonglong2 a01 = *(const ulonglong2*)&Xs[buf][kk][mw];
            ulonglong2 a23 = *(const ulonglong2*)&Xs[buf][kk][mw + 4];
            float4 w = *(const float4*)&Ws[buf][kk][j4];
            u64 w0, w1, w2, w3;
            DUP2(w0, w.x); DUP2(w1, w.y); DUP2(w2, w.z); DUP2(w3, w.w);
            FMA2(acc[0][0], a01.x, w0); FMA2(acc[0][1], a01.x, w1);
            FMA2(acc[0][2], a01.x, w2); FMA2(acc[0][3], a01.x, w3);
            FMA2(acc[1][0], a01.y, w0); FMA2(acc[1][1], a01.y, w1);
            FMA2(acc[1][2], a01.y, w2); FMA2(acc[1][3], a01.y, w3);
            FMA2(acc[2][0], a23.x, w0); FMA2(acc[2][1], a23.x, w1);
            FMA2(acc[2][2], a23.x, w2); FMA2(acc[2][3], a23.x, w3);
            FMA2(acc[3][0], a23.y, w0); FMA2(acc[3][1], a23.y, w1);
            FMA2(acc[3][2], a23.y, w2); FMA2(acc[3][3], a23.y, w3);
        }
        buf ^= 1;
    }

    // ---- epilogue ----
    int Mtot = (mode == M_ATT) ? (N_B * NWIN) : N_B;
    #pragma unroll
    for (int p = 0; p < 4; p++) {
        int r0 = mw + 2 * p;
        #pragma unroll
        for (int q = 0; q < 4; q++) {
            float vlo, vhi;
            UNPK(vlo, vhi, acc[p][q]);
            int jg = j0 + j4 + q;
            switch (mode) {
                case M_P1: {
                    float b = P.b_p1[jg];
                    g_p1[(m0 + r0) * 512 + jg]     = fmaxf(vlo + b, 0.f);
                    g_p1[(m0 + r0 + 1) * 512 + jg] = fmaxf(vhi + b, 0.f);
                } break;
                case M_SP2: {
                    float b = P.b_sp2[jg];
                    g_sp[(m0 + r0) * ENC + jg]     = tanhf(vlo + b);
                    g_sp[(m0 + r0 + 1) * ENC + jg] = tanhf(vhi + b);
                } break;
                case M_SB: {
                    g_sb[(m0 + r0) * ATT + jg]     = vlo / (1.f + fabsf(vlo));
                    g_sb[(m0 + r0 + 1) * ATT + jg] = vhi / (1.f + fabsf(vhi));
                } break;
                case M_P2: {
                    size_t base = ((size_t)s * N_B + (m0 + r0)) * ATT + jg;
                    g_parts2[base] = vlo; g_parts2[base + ATT] = vhi;
                } break;
                default: {
                    if (jg < J) {
                        size_t base = ((size_t)s * Mtot + (m0 + r0)) * J + jg;
                        g_parts[base] = vlo; g_parts[base + J] = vhi;
                    }
                } break;
            }
        }
    }
}

// ---------------------------------------------------------------------------
// LSTM activation: float4, gates i,g,o at cols u, 1024+u, 2048+u of G3 rows.
// Needs exactly 64 * 256 threads.
// ---------------------------------------------------------------------------
__global__ void lstm_act(int layer, const float* __restrict__ bih,
                         const float* __restrict__ bhh)
{
    int idx = blockIdx.x * 256 + threadIdx.x;
    if (idx >= N_B * 256) return;               // guard (grid must be 64 blocks)
    int n = idx >> 8, u4 = (idx & 255) * 4;
    float4 bi = *(const float4*)(bih + u4);
    float4 bj = *(const float4*)(bhh + u4);
    float4 bg = *(const float4*)(bih + 2048 + u4);
    float4 bG = *(const float4*)(bhh + 2048 + u4);
    float4 bo = *(const float4*)(bih + 3072 + u4);
    float4 bO = *(const float4*)(bhh + 3072 + u4);
    float gi[4] = {bi.x + bj.x, bi.y + bj.y, bi.z + bj.z, bi.w + bj.w};
    float gg[4] = {bg.x + bG.x, bg.y + bG.y, bg.z + bG.z, bg.w + bG.w};
    float go[4] = {bo.x + bO.x, bo.y + bO.y, bo.z + bO.z, bo.w + bO.w};
    #pragma unroll
    for (int s = 0; s < S_L; s++) {
        size_t base = ((size_t)s * N_B + n) * G3;
        float4 a = *(const float4*)(g_parts + base + u4);
        float4 b = *(const float4*)(g_parts + base + 1024 + u4);
        float4 c = *(const float4*)(g_parts + base + 2048 + u4);
        gi[0] += a.x; gi[1] += a.y; gi[2] += a.z; gi[3] += a.w;
        gg[0] += b.x; gg[1] += b.y; gg[2] += b.z; gg[3] += b.w;
        go[0] += c.x; go[1] += c.y; go[2] += c.z; go[3] += c.w;
    }
    float4 h;
    float* hp = &h.x;
    #pragma unroll
    for (int q = 0; q < 4; q++) {
        float c = sigm(gi[q]) * tanhf(gg[q]);
        hp[q] = sigm(go[q]) * tanhf(c);
    }
    if (layer == 0) *(float4*)(g_h1 + n * H4 + u4) = h;
    else            *(float4*)(g_dec + (size_t)n * DECCAT + u4) = h;
}

__global__ void out_finish(const float* __restrict__ b_out, float* __restrict__ out)
{
    int n = blockIdx.x;
    int j = threadIdx.x;    // 160
    float a = b_out[j];
    #pragma unroll
    for (int s = 0; s < S_OUT; s++)
        a += g_parts[((size_t)s * N_B + n) * OUT_J + j];
    out[n * OUT_J + j] = a;
}

// ---------------------------------------------------------------------------
extern "C" void kernel_launch(void* const* d_in, const int* in_sizes, int n_in,
                              void* d_out, int out_size)
{
    Ptrs P;
    P.input_enc   = (const float*)d_in[0];
    P.input_dec   = (const float*)d_in[1];
    P.spkr        = (const float*)d_in[2];
    P.lengths     = (const int*)  d_in[3];
    P.speed       = (const float*)d_in[4];
    P.W_enc       = (const float*)d_in[5];
    P.b_enc       = (const float*)d_in[6];
    P.W_spkr      = (const float*)d_in[7];
    P.conv_prev   = (const float*)d_in[8];
    P.W_speed_att = (const float*)d_in[9];
    P.W_proj      = (const float*)d_in[10];
    P.b_proj      = (const float*)d_in[11];
    P.W_sp1       = (const float*)d_in[12];
    P.b_sp1       = (const float*)d_in[13];
    P.W_sp2       = (const float*)d_in[14];
    P.b_sp2       = (const float*)d_in[15];
    P.W_p1        = (const float*)d_in[16];
    P.b_p1        = (const float*)d_in[17];
    P.W_p2        = (const float*)d_in[18];
    P.b_p2        = (const float*)d_in[19];
    P.Wih0        = (const float*)d_in[20];
    P.bih0        = (const float*)d_in[22];
    P.bhh0        = (const float*)d_in[23];
    P.Wih1        = (const float*)d_in[24];
    P.bih1        = (const float*)d_in[26];
    P.bhh1        = (const float*)d_in[27];
    P.W_out       = (const float*)d_in[28];
    P.b_out       = (const float*)d_in[29];

    float* out = (float*)d_out;
    P.out = out;
    P.write_ctx = (out_size >= N_B * 2 * 80 + N_B * ENC) ? 1 : 0;
    P.ctx_out = out + N_B * 2 * 80;

    // L1: att-bias GEMM (80) + prenet1 (4) + speed-proj2 (4) + spkr-bias (2)
    stage_k<<<90, 256>>>(1, P);
    // L2: att epilogue/context/in_lstm (64) + prenet2 partial GEMM (4)
    stage_k<<<68, 256>>>(2, P);
    // L3: LSTM0 GEMM (i,g,o only), 24 j-tiles x 6 splits = 144 blocks
    stage_k<<<144, 256>>>(3, P);
    lstm_act<<<64, 256>>>(0, P.bih0, P.bhh0);
    // L5: LSTM1 GEMM
    stage_k<<<144, 256>>>(4, P);
    lstm_act<<<64, 256>>>(1, P.bih1, P.bhh1);
    // L7: output GEMM
    stage_k<<<16, 256>>>(5, P);
    out_finish<<<64, 160>>>(P.b_out, out);
}

// round 5
// speedup vs baseline: 3.6906x; 1.2868x over previous
#include <cuda_runtime.h>
#include <math.h>
#include <stddef.h>

// ---------------------------------------------------------------------------
// AttnDecoderRNN2 single step, algebraically reduced (validated):
//  * attention window always t in [0,9]; softmax max cancels in L1 norm
//  * zero LSTM state -> Whh unused, f-gate dead (i,g,o rows only: J=3072)
// Round 5: ONE persistent kernel (148 blocks, device-wide barriers). Round-4
// ncu showed ~5-7us fixed overhead per launch (lstm_act: <1us work, 7.5us
// wall) -> 8 nodes ~= 50us pure overhead. Stage outputs consumed via __ldcg
// (L1 not coherent across SMs; scratch reused across stages).
// ---------------------------------------------------------------------------

#define GRID    148
#define N_B     64
#define T_ENC   2000
#define ENC     512
#define ATT     256
#define H4      1024
#define G3      3072
#define IN_LSTM 832
#define DECCAT  1536
#define NWIN    10
#define OUT_J   160

#define S_ATT 6
#define S_SP2 4
#define S_P2  8
#define S_L   6
#define S_OUT 32

typedef unsigned long long u64;

// scratch (device globals; allocation forbidden)
__device__ __align__(16) float g_att_parts[S_ATT * 640 * ATT];
__device__ __align__(16) float g_p1_parts [2 * N_B * 512];
__device__ __align__(16) float g_sp2_parts[S_SP2 * N_B * 512];
__device__ __align__(16) float g_p2_parts [S_P2 * N_B * 256];
__device__ __align__(16) float g_sb       [N_B * ATT];
__device__ __align__(16) float g_lstm_parts[S_L * N_B * G3];
__device__ __align__(16) float g_out_parts[S_OUT * N_B * OUT_J];
__device__ __align__(16) float g_inlstm   [N_B * IN_LSTM];   // cols 256.. used
__device__ __align__(16) float g_h1       [N_B * H4];
__device__ __align__(16) float g_dec      [N_B * DECCAT];    // [h2 | context]

// grid barrier state
__device__ unsigned g_cnt = 0;
__device__ volatile unsigned g_sense = 0;

struct Ptrs {
    const float *input_enc, *input_dec, *spkr, *speed;
    const float *W_enc, *b_enc, *W_spkr, *conv_prev, *W_speed_att, *W_proj, *b_proj;
    const float *W_sp1, *b_sp1, *W_sp2, *b_sp2;
    const float *W_p1, *b_p1, *W_p2, *b_p2;
    const float *Wih0, *bih0, *bhh0, *Wih1, *bih1, *bhh1, *W_out, *b_out;
    const int *lengths;
    float *out, *ctx_out;
    int write_ctx;
};

__device__ __forceinline__ float sigm(float x) { return 1.f / (1.f + expf(-x)); }

#define FMA2(d, a, b) asm("fma.rn.f32x2 %0,%1,%2,%0;" : "+l"(d) : "l"(a), "l"(b))
#define DUP2(d, s)    asm("mov.b64 %0,{%1,%1};" : "=l"(d) : "f"(s))
#define UNPK(lo, hi, v) asm("mov.b64 {%0,%1},%2;" : "=f"(lo), "=f"(hi) : "l"(v))

enum { M_ATT = 0, M_P1, M_SP2, M_SB, M_P2, M_L0, M_L1, M_OUT };

// ---------------------------------------------------------------------------
__device__ __forceinline__ void gbar(unsigned target)
{
    __syncthreads();
    if (threadIdx.x == 0) {
        __threadfence();
        if (atomicAdd(&g_cnt, 1) == GRID - 1) {
            g_cnt = 0;
            __threadfence();
            g_sense = target;
        } else {
            while (g_sense != target) __nanosleep(32);
        }
        __threadfence();
    }
    __syncthreads();
}

// ---------------------------------------------------------------------------
// unified double-buffered GEMM tile. 64m x 128j x chunk-k, 256 threads.
// ---------------------------------------------------------------------------
__device__ __noinline__ void gemm_tile(int mode, int jt, int s, int mt,
                                       const Ptrs& P,
                                       float (*Xs)[16][68], float (*Ws)[16][132])
{
    int K, chunk, J;
    const float* W;
    switch (mode) {
        case M_ATT: K = 512;  chunk = 96;  J = 256;   W = P.W_enc;  break;
        case M_P1:  K = 144;  chunk = 80;  J = 512;   W = P.W_p1;   break;
        case M_SP2: K = 256;  chunk = 64;  J = 512;   W = P.W_sp2;  break;
        case M_SB:  K = 64;   chunk = 64;  J = 256;   W = P.W_spkr; break;
        case M_P2:  K = 512;  chunk = 64;  J = 256;   W = P.W_p2;   break;
        case M_L0:  K = 832;  chunk = 144; J = G3;    W = P.Wih0;   break;
        case M_L1:  K = 1024; chunk = 176; J = G3;    W = P.Wih1;   break;
        default:    K = 1536; chunk = 48;  J = OUT_J; W = P.W_out;  break;
    }
    int lstm = (mode == M_L0 || mode == M_L1);
    int j0 = jt * 128, m0 = mt * 64;
    int kbeg = s * chunk;
    int kend = min(K, kbeg + chunk);
    int nsl  = (kend - kbeg) >> 4;

    int tid  = threadIdx.x;
    int mrow = tid >> 2;
    int kc   = (tid & 3) * 4;
    int mg   = m0 + mrow;

    const float* xrow = 0; float spd = 0.f;
    switch (mode) {
        case M_ATT: { int n = mg / 10; int t = mg - n * 10;
                      xrow = P.input_enc + ((size_t)n * T_ENC + t) * ENC; } break;
        case M_P1:  xrow = P.input_dec + mg * 80; break;
        case M_SP2: spd = P.speed[mg]; break;
        case M_SB:  xrow = P.spkr + mg * 64; break;
        case M_P2:  break;   // from p1 partials
        case M_L0:  xrow = g_inlstm + mg * IN_LSTM; break;
        case M_L1:  xrow = g_h1 + (size_t)mg * H4; break;
        default:    xrow = g_dec + (size_t)mg * DECCAT; break;
    }
    // W rows (lstm: skip dead f-gate rows: logical [1024,3072) -> phys +1024)
    int gj0 = j0 + mrow, gj1 = j0 + 64 + mrow;
    int jp0 = lstm ? (gj0 + (gj0 >= 1024 ? 1024 : 0)) : gj0;
    int jp1 = lstm ? (gj1 + (gj1 >= 1024 ? 1024 : 0)) : gj1;
    const float* wp0 = W + (size_t)jp0 * K;
    const float* wp1 = W + (size_t)jp1 * K;
    bool v0 = gj0 < J, v1 = gj1 < J;

    int warp = tid >> 5, lane = tid & 31;
    int mw = warp * 8;
    int j4 = lane * 4;
    u64 acc[4][4] = {};

    auto load_x = [&](int kg) -> float4 {
        float4 xv;
        if (mode == M_SP2) {
            float4 w1 = *(const float4*)(P.W_sp1 + kg);
            float4 b1 = *(const float4*)(P.b_sp1 + kg);
            xv.x = fmaxf(spd * w1.x + b1.x, 0.f);
            xv.y = fmaxf(spd * w1.y + b1.y, 0.f);
            xv.z = fmaxf(spd * w1.z + b1.z, 0.f);
            xv.w = fmaxf(spd * w1.w + b1.w, 0.f);
        } else if (mode == M_P1) {
            xv = (kg < 80) ? *(const float4*)(xrow + kg)
                           : *(const float4*)(P.spkr + mg * 64 + (kg - 80));
        } else if (mode == M_P2) {
            float4 bb = *(const float4*)(P.b_p1 + kg);
            float4 pa = __ldcg((const float4*)(g_p1_parts + (size_t)mg * 512 + kg));
            float4 pb = __ldcg((const float4*)(g_p1_parts + (size_t)(N_B + mg) * 512 + kg));
            xv.x = fmaxf(bb.x + pa.x + pb.x, 0.f);
            xv.y = fmaxf(bb.y + pa.y + pb.y, 0.f);
            xv.z = fmaxf(bb.z + pa.z + pb.z, 0.f);
            xv.w = fmaxf(bb.w + pa.w + pb.w, 0.f);
        } else if (mode == M_L0 && kg < 256) {
            float4 a4 = *(const float4*)(P.b_p2 + kg);
            #pragma unroll
            for (int s2 = 0; s2 < S_P2; s2++) {
                float4 pp = __ldcg((const float4*)(g_p2_parts + (size_t)(s2 * N_B + mg) * 256 + kg));
                a4.x += pp.x; a4.y += pp.y; a4.z += pp.z; a4.w += pp.w;
            }
            xv.x = fmaxf(a4.x, 0.f); xv.y = fmaxf(a4.y, 0.f);
            xv.z = fmaxf(a4.z, 0.f); xv.w = fmaxf(a4.w, 0.f);
        } else if (mode == M_L0 || mode == M_L1 || mode == M_OUT) {
            xv = __ldcg((const float4*)(xrow + kg));
        } else {
            xv = *(const float4*)(xrow + kg);
        }
        return xv;
    };

    float4 xv = load_x(kbeg + kc);
    float4 wv0 = v0 ? *(const float4*)(wp0 + kbeg + kc) : make_float4(0, 0, 0, 0);
    float4 wv1 = v1 ? *(const float4*)(wp1 + kbeg + kc) : make_float4(0, 0, 0, 0);

    int buf = 0;
    for (int i = 0; i < nsl; i++) {
        Xs[buf][kc + 0][mrow] = xv.x; Xs[buf][kc + 1][mrow] = xv.y;
        Xs[buf][kc + 2][mrow] = xv.z; Xs[buf][kc + 3][mrow] = xv.w;
        Ws[buf][kc + 0][mrow] = wv0.x; Ws[buf][kc + 1][mrow] = wv0.y;
        Ws[buf][kc + 2][mrow] = wv0.z; Ws[buf][kc + 3][mrow] = wv0.w;
        Ws[buf][kc + 0][64 + mrow] = wv1.x; Ws[buf][kc + 1][64 + mrow] = wv1.y;
        Ws[buf][kc + 2][64 + mrow] = wv1.z; Ws[buf][kc + 3][64 + mrow] = wv1.w;
        __syncthreads();

        if (i + 1 < nsl) {
            int kg = kbeg + (i + 1) * 16 + kc;
            xv  = load_x(kg);
            wv0 = v0 ? *(const float4*)(wp0 + kg) : make_float4(0, 0, 0, 0);
            wv1 = v1 ? *(const float4*)(wp1 + kg) : make_float4(0, 0, 0, 0);
        }

        #pragma unroll
        for (int kk = 0; kk < 16; kk++) {
            ulonglong2 a01 = *(const ulonglong2*)&Xs[buf][kk][mw];
            ulonglong2 a23 = *(const ulonglong2*)&Xs[buf][kk][mw + 4];
            float4 w = *(const float4*)&Ws[buf][kk][j4];
            u64 w0, w1, w2, w3;
            DUP2(w0, w.x); DUP2(w1, w.y); DUP2(w2, w.z); DUP2(w3, w.w);
            FMA2(acc[0][0], a01.x, w0); FMA2(acc[0][1], a01.x, w1);
            FMA2(acc[0][2], a01.x, w2); FMA2(acc[0][3], a01.x, w3);
            FMA2(acc[1][0], a01.y, w0); FMA2(acc[1][1], a01.y, w1);
            FMA2(acc[1][2], a01.y, w2); FMA2(acc[1][3], a01.y, w3);
            FMA2(acc[2][0], a23.x, w0); FMA2(acc[2][1], a23.x, w1);
            FMA2(acc[2][2], a23.x, w2); FMA2(acc[2][3], a23.x, w3);
            FMA2(acc[3][0], a23.y, w0); FMA2(acc[3][1], a23.y, w1);
            FMA2(acc[3][2], a23.y, w2); FMA2(acc[3][3], a23.y, w3);
        }
        __syncthreads();
        buf ^= 1;
    }

    #pragma unroll
    for (int p = 0; p < 4; p++) {
        int r0 = m0 + mw + 2 * p;
        #pragma unroll
        for (int q = 0; q < 4; q++) {
            float vlo, vhi;
            UNPK(vlo, vhi, acc[p][q]);
            int jg = j0 + j4 + q;
            switch (mode) {
                case M_ATT: {
                    size_t base = ((size_t)s * 640 + r0) * ATT + jg;
                    g_att_parts[base] = vlo; g_att_parts[base + ATT] = vhi;
                } break;
                case M_P1: {
                    size_t base = ((size_t)s * N_B + r0) * 512 + jg;
                    g_p1_parts[base] = vlo; g_p1_parts[base + 512] = vhi;
                } break;
                case M_SP2: {
                    size_t base = ((size_t)s * N_B + r0) * 512 + jg;
                    g_sp2_parts[base] = vlo; g_sp2_parts[base + 512] = vhi;
                } break;
                case M_SB: {
                    g_sb[r0 * ATT + jg]       = vlo / (1.f + fabsf(vlo));
                    g_sb[(r0 + 1) * ATT + jg] = vhi / (1.f + fabsf(vhi));
                } break;
                case M_P2: {
                    size_t base = ((size_t)s * N_B + r0) * 256 + jg;
                    g_p2_parts[base] = vlo; g_p2_parts[base + 256] = vhi;
                } break;
                case M_OUT: {
                    if (jg < OUT_J) {
                        size_t base = ((size_t)s * N_B + r0) * OUT_J + jg;
                        g_out_parts[base] = vlo; g_out_parts[base + OUT_J] = vhi;
                    }
                } break;
                default: {   // L0 / L1
                    size_t base = ((size_t)s * N_B + r0) * G3 + jg;
                    g_lstm_parts[base] = vlo; g_lstm_parts[base + G3] = vhi;
                } break;
            }
        }
    }
}

// ---------------------------------------------------------------------------
__device__ void att_finish_dev(int n, const Ptrs& P)
{
    __shared__ float red[80];
    __shared__ float logit_s[NWIN];
    __shared__ float att_s[NWIN];

    int a = threadIdx.x;          // 256
    int warp = a >> 5, lane = a & 31;

    float sb    = __ldcg(&g_sb[n * ATT + a]);
    float spw   = P.speed[n] * P.W_speed_att[a];
    float wproj = P.W_proj[a];
    float be    = P.b_enc[a];

    float v[NWIN];
    #pragma unroll
    for (int t = 0; t < NWIN; t++) {
        float dot = be;
        #pragma unroll
        for (int s = 0; s < S_ATT; s++)
            dot += __ldcg(&g_att_parts[((size_t)s * 640 + n * 10 + t) * ATT + a]);
        float eb = dot / (1.f + fabsf(dot));
        float e  = eb + sb + P.conv_prev[a * 31 + (15 - t)] + spw;
        v[t] = tanhf(e) * wproj;
    }
    #pragma unroll
    for (int t = 0; t < NWIN; t++) {
        #pragma unroll
        for (int o = 16; o > 0; o >>= 1)
            v[t] += __shfl_xor_sync(0xffffffffu, v[t], o);
    }
    if (lane == 0) {
        #pragma unroll
        for (int t = 0; t < NWIN; t++) red[warp * NWIN + t] = v[t];
    }
    __syncthreads();
    if (a < NWIN) {
        float s = 0.f;
        #pragma unroll
        for (int w = 0; w < 8; w++) s += red[w * NWIN + a];
        logit_s[a] = s + P.b_proj[0];
    }
    __syncthreads();
    if (a == 0) {
        int len1 = max(P.lengths[n], 1) - 1;
        int hi = min(9, len1);
        float m = -1e30f;
        for (int t = 0; t <= hi; t++) m = fmaxf(m, logit_s[t]);
        float ss = 0.f;
        for (int t = 0; t < NWIN; t++) {
            float w = (t <= hi) ? expf(logit_s[t] - m) : 0.f;
            att_s[t] = w; ss += w;
        }
        float inv = 1.f / fmaxf(ss, 1e-12f);
        for (int t = 0; t < NWIN; t++) att_s[t] *= inv;
    }
    __syncthreads();

    // context = tanh(sp2 sum) + sum_t att_t * enc[t]   (sum att = 1)
    for (int e = a; e < ENC; e += 256) {
        float spv = P.b_sp2[e];
        #pragma unroll
        for (int s = 0; s < S_SP2; s++)
            spv += __ldcg(&g_sp2_parts[((size_t)s * N_B + n) * 512 + e]);
        float c = tanhf(spv);
        #pragma unroll
        for (int t = 0; t < NWIN; t++)
            c += att_s[t] * P.input_enc[((size_t)n * T_ENC + t) * ENC + e];
        g_inlstm[n * IN_LSTM + 256 + e] = c;
        g_dec[(size_t)n * DECCAT + H4 + e] = c;
        if (P.write_ctx) P.ctx_out[n * ENC + e] = c;
    }
    if (a < 64) g_inlstm[n * IN_LSTM + 768 + a] = P.spkr[n * 64 + a];
}

// ---------------------------------------------------------------------------
__device__ void act_dev(int layer, const Ptrs& P)
{
    const float* bih = layer ? P.bih1 : P.bih0;
    const float* bhh = layer ? P.bhh1 : P.bhh0;
    for (int idx = blockIdx.x * 256 + threadIdx.x; idx < N_B * H4; idx += GRID * 256) {
        int n = idx >> 10, u = idx & 1023;
        float gi = bih[u] + bhh[u];
        float gg = bih[2048 + u] + bhh[2048 + u];
        float go = bih[3072 + u] + bhh[3072 + u];
        #pragma unroll
        for (int s = 0; s < S_L; s++) {
            const float* p = g_lstm_parts + ((size_t)s * N_B + n) * G3;
            gi += __ldcg(p + u);
            gg += __ldcg(p + 1024 + u);
            go += __ldcg(p + 2048 + u);
        }
        float c = sigm(gi) * tanhf(gg);
        float h = sigm(go) * tanhf(c);
        if (layer == 0) g_h1[n * H4 + u] = h;
        else            g_dec[(size_t)n * DECCAT + u] = h;
    }
}

// ---------------------------------------------------------------------------
__global__ void __launch_bounds__(256, 1) fused_k(Ptrs P)
{
    __shared__ __align__(16) float Xs[2][16][68];
    __shared__ __align__(16) float Ws[2][16][132];

    unsigned s0 = 0;
    if (threadIdx.x == 0) s0 = g_sense;
    int b = blockIdx.x;

    // ---- stage A: ATT(120) + P1(8) + SP2(16) + SB(2) = 146 tasks ----
    if (b < 146) {
        int mode, jt, s = 0, mt = 0;
        if (b < 120)      { mode = M_ATT; jt = b & 1; int r = b >> 1; s = r % 6; mt = r / 6; }
        else if (b < 128) { int t = b - 120; mode = M_P1;  jt = t & 3; s = t >> 2; }
        else if (b < 144) { int t = b - 128; mode = M_SP2; jt = t & 3; s = t >> 2; }
        else              { mode = M_SB;  jt = b - 144; }
        gemm_tile(mode, jt, s, mt, P, Xs, Ws);
    }
    gbar(s0 + 1);

    // ---- stage B: att_finish(64) + P2 GEMM(16) ----
    if (b < 64) att_finish_dev(b, P);
    else if (b < 80) { int t = b - 64; gemm_tile(M_P2, t & 1, t >> 1, 0, P, Xs, Ws); }
    gbar(s0 + 2);

    // ---- stage C: LSTM0 GEMM (24 jt x 6 s = 144), prenet2 act fused in loader
    if (b < 144) gemm_tile(M_L0, b % 24, b / 24, 0, P, Xs, Ws);
    gbar(s0 + 3);

    // ---- stage D: LSTM0 activation ----
    act_dev(0, P);
    gbar(s0 + 4);

    // ---- stage E: LSTM1 GEMM ----
    if (b < 144) gemm_tile(M_L1, b % 24, b / 24, 0, P, Xs, Ws);
    gbar(s0 + 5);

    // ---- stage F: LSTM1 activation ----
    act_dev(1, P);
    gbar(s0 + 6);

    // ---- stage G: output GEMM (2 jt x 32 s = 64) ----
    if (b < 64) gemm_tile(M_OUT, b & 1, b >> 1, 0, P, Xs, Ws);
    gbar(s0 + 7);

    // ---- stage H: output reduction ----
    int gt = b * 256 + threadIdx.x;
    if (gt < N_B * OUT_J) {
        int n = gt / OUT_J, j = gt - n * OUT_J;
        float a = P.b_out[j];
        #pragma unroll
        for (int s = 0; s < S_OUT; s++)
            a += __ldcg(&g_out_parts[((size_t)s * N_B + n) * OUT_J + j]);
        P.out[n * OUT_J + j] = a;
    }
}

// ---------------------------------------------------------------------------
extern "C" void kernel_launch(void* const* d_in, const int* in_sizes, int n_in,
                              void* d_out, int out_size)
{
    Ptrs P;
    P.input_enc   = (const float*)d_in[0];
    P.input_dec   = (const float*)d_in[1];
    P.spkr        = (const float*)d_in[2];
    P.lengths     = (const int*)  d_in[3];
    P.speed       = (const float*)d_in[4];
    P.W_enc       = (const float*)d_in[5];
    P.b_enc       = (const float*)d_in[6];
    P.W_spkr      = (const float*)d_in[7];
    P.conv_prev   = (const float*)d_in[8];
    P.W_speed_att = (const float*)d_in[9];
    P.W_proj      = (const float*)d_in[10];
    P.b_proj      = (const float*)d_in[11];
    P.W_sp1       = (const float*)d_in[12];
    P.b_sp1       = (const float*)d_in[13];
    P.W_sp2       = (const float*)d_in[14];
    P.b_sp2       = (const float*)d_in[15];
    P.W_p1        = (const float*)d_in[16];
    P.b_p1        = (const float*)d_in[17];
    P.W_p2        = (const float*)d_in[18];
    P.b_p2        = (const float*)d_in[19];
    P.Wih0        = (const float*)d_in[20];
    P.bih0        = (const float*)d_in[22];
    P.bhh0        = (const float*)d_in[23];
    P.Wih1        = (const float*)d_in[24];
    P.bih1        = (const float*)d_in[26];
    P.bhh1        = (const float*)d_in[27];
    P.W_out       = (const float*)d_in[28];
    P.b_out       = (const float*)d_in[29];

    float* out = (float*)d_out;
    P.out = out;
    P.write_ctx = (out_size >= N_B * 2 * 80 + N_B * ENC) ? 1 : 0;
    P.ctx_out = out + N_B * 2 * 80;

    fused_k<<<GRID, 256>>>(P);
}